// round 1
// baseline (speedup 1.0000x reference)
#include <cuda_runtime.h>
#include <cstddef>

#define BB 32
#define CC 128
#define HH 72
#define WW 200
#define KS 9

// ---------------------------------------------------------------------------
// One recurrence step of an H-direction sweep (conv along W, pad 4):
//   buf[b, co, r, w] += relu( bias[co] + sum_{ci,k} buf[b, ci, pr, w+k-4] * wgt[co, ci, k] )
// In-place is safe: row r holds the previous sweep's value until we write it,
// row pr was written by the previous launch (stream-ordered, L1D flushed per launch).
// Grid: (4 co-blocks of 32, 32 batches). Block: 256 threads.
// Thread tile: 2 co x 13 w (16 co-groups x 16 w-groups covers 208 >= 200).
// ---------------------------------------------------------------------------
__global__ __launch_bounds__(256) void hstep(
    float* __restrict__ buf, const float* __restrict__ wgt,
    const float* __restrict__ bias, int r, int pr)
{
    __shared__ float pS[16 * 216];       // prev-row slice, 16 ci, x = w + 4 (zero-padded)
    __shared__ float wS[16 * 9 * 32];    // weight tile [ci][k][co]

    const int b   = blockIdx.y;
    const int co0 = blockIdx.x * 32;
    const int tid = threadIdx.x;
    const int tc  = tid & 15;            // co-pair group: co = co0 + 2*tc
    const int tw  = tid >> 4;            // 0..15
    const int wb  = tw * 13;

    float acc0[13], acc1[13];
#pragma unroll
    for (int j = 0; j < 13; ++j) { acc0[j] = 0.f; acc1[j] = 0.f; }

    const size_t bbase = (size_t)b * CC * HH * WW;
    const float* prow  = buf + bbase + (size_t)pr * WW;   // + ci*H*W + w

#pragma unroll 1
    for (int cb = 0; cb < 8; ++cb) {
        const int ci0 = cb * 16;
        __syncthreads();
        // Stage prev row (ci-block) with zero pad; coalesced along w.
        for (int i = tid; i < 16 * 216; i += 256) {
            int ci = i / 216;
            int x  = i - ci * 216;
            int w  = x - 4;
            float v = 0.f;
            if (w >= 0 && w < WW) v = prow[(size_t)(ci0 + ci) * (HH * WW) + w];
            pS[i] = v;
        }
        // Stage weights: per co, 144 contiguous floats (16 ci x 9 k). Coalesced.
        for (int i = tid; i < 32 * 144; i += 256) {
            int c = i / 144;
            int f = i - c * 144;                       // f = ci*9 + k
            wS[f * 32 + c] = wgt[(size_t)(co0 + c) * (CC * KS) + ci0 * KS + f];
        }
        __syncthreads();
#pragma unroll 1
        for (int ci = 0; ci < 16; ++ci) {
            float p[21];                               // sliding window: 13 outputs + 8 taps
#pragma unroll
            for (int j = 0; j < 21; ++j) p[j] = pS[ci * 216 + wb + j];
            const float* wr = &wS[ci * 9 * 32];
#pragma unroll
            for (int k = 0; k < 9; ++k) {
                float w0 = wr[k * 32 + 2 * tc];
                float w1 = wr[k * 32 + 2 * tc + 1];
#pragma unroll
                for (int j = 0; j < 13; ++j) {
                    acc0[j] = fmaf(w0, p[j + k], acc0[j]);
                    acc1[j] = fmaf(w1, p[j + k], acc1[j]);
                }
            }
        }
    }

    const int coA = co0 + 2 * tc;
    const float bA = bias[coA];
    const float bB = bias[coA + 1];
    float* rowA = buf + bbase + (size_t)coA * (HH * WW) + (size_t)r * WW;
    float* rowB = rowA + (size_t)(HH * WW);
#pragma unroll
    for (int j = 0; j < 13; ++j) {
        int w = wb + j;
        if (w < WW) {
            float tA = acc0[j] + bA;
            float tB = acc1[j] + bB;
            rowA[w] += tA > 0.f ? tA : 0.f;
            rowB[w] += tB > 0.f ? tB : 0.f;
        }
    }
}

// ---------------------------------------------------------------------------
// One recurrence step of a W-direction sweep (conv along H, pad 4):
//   buf[b, co, h, r] += relu( bias[co] + sum_{ci,k} buf[b, ci, h+k-4, pr] * wgt[co, ci, k] )
// Thread tile: 1 co x 9 h (32 co-groups x 8 h-groups = exact 72-row cover, zero waste).
// ---------------------------------------------------------------------------
__global__ __launch_bounds__(256) void wstep(
    float* __restrict__ buf, const float* __restrict__ wgt,
    const float* __restrict__ bias, int r, int pr)
{
    __shared__ float pS[16 * 80];        // prev-column slice, x = h + 4 (zero-padded)
    __shared__ float wS[16 * 9 * 32];

    const int b   = blockIdx.y;
    const int co0 = blockIdx.x * 32;
    const int tid = threadIdx.x;
    const int tc  = tid & 31;            // co = co0 + tc
    const int th  = tid >> 5;            // 0..7
    const int hb  = th * 9;

    float acc[9];
#pragma unroll
    for (int j = 0; j < 9; ++j) acc[j] = 0.f;

    const size_t bbase = (size_t)b * CC * HH * WW;
    const float* pcol  = buf + bbase + pr;               // + ci*H*W + h*W

#pragma unroll 1
    for (int cb = 0; cb < 8; ++cb) {
        const int ci0 = cb * 16;
        __syncthreads();
        for (int i = tid; i < 16 * 80; i += 256) {
            int ci = i / 80;
            int x  = i - ci * 80;
            int h  = x - 4;
            float v = 0.f;
            if (h >= 0 && h < HH)
                v = pcol[(size_t)(ci0 + ci) * (HH * WW) + (size_t)h * WW];
            pS[i] = v;
        }
        for (int i = tid; i < 32 * 144; i += 256) {
            int c = i / 144;
            int f = i - c * 144;
            wS[f * 32 + c] = wgt[(size_t)(co0 + c) * (CC * KS) + ci0 * KS + f];
        }
        __syncthreads();
#pragma unroll 1
        for (int ci = 0; ci < 16; ++ci) {
            float p[17];                                // 9 outputs + 8 taps
#pragma unroll
            for (int j = 0; j < 17; ++j) p[j] = pS[ci * 80 + hb + j];
            const float* wr = &wS[ci * 9 * 32];
#pragma unroll
            for (int k = 0; k < 9; ++k) {
                float w0 = wr[k * 32 + tc];
#pragma unroll
                for (int j = 0; j < 9; ++j)
                    acc[j] = fmaf(w0, p[j + k], acc[j]);
            }
        }
    }

    const int co = co0 + tc;
    const float bs = bias[co];
    float* colp = buf + bbase + (size_t)co * (HH * WW) + r;
#pragma unroll
    for (int j = 0; j < 9; ++j) {
        int h = hb + j;
        float t = acc[j] + bs;
        colp[(size_t)h * WW] += t > 0.f ? t : 0.f;
    }
}

// ---------------------------------------------------------------------------
// Launcher: copy x -> out, then 4 in-place sweeps as chains of step kernels.
// Everything is default-stream, graph-capturable, allocation-free.
// ---------------------------------------------------------------------------
extern "C" void kernel_launch(void* const* d_in, const int* in_sizes, int n_in,
                              void* d_out, int out_size)
{
    const float* x  = (const float*)d_in[0];
    const float* wd = (const float*)d_in[1];
    const float* bd = (const float*)d_in[2];
    const float* wu = (const float*)d_in[3];
    const float* bu = (const float*)d_in[4];
    const float* wr = (const float*)d_in[5];
    const float* br = (const float*)d_in[6];
    const float* wl = (const float*)d_in[7];
    const float* bl = (const float*)d_in[8];
    float* out = (float*)d_out;

    const size_t bytes = (size_t)BB * CC * HH * WW * sizeof(float);
    cudaMemcpyAsync(out, x, bytes, cudaMemcpyDeviceToDevice);

    dim3 grid(4, BB);

    // Sweep D: axis H, forward
    for (int h = 1; h < HH; ++h)
        hstep<<<grid, 256>>>(out, wd, bd, h, h - 1);
    // Sweep U: axis H, reverse
    for (int h = HH - 2; h >= 0; --h)
        hstep<<<grid, 256>>>(out, wu, bu, h, h + 1);
    // Sweep R: axis W, forward
    for (int w = 1; w < WW; ++w)
        wstep<<<grid, 256>>>(out, wr, br, w, w - 1);
    // Sweep L: axis W, reverse
    for (int w = WW - 2; w >= 0; --w)
        wstep<<<grid, 256>>>(out, wl, bl, w, w + 1);
}

// round 2
// speedup vs baseline: 1.0006x; 1.0006x over previous
#include <cuda_runtime.h>
#include <cstddef>

#define BB 32
#define CC 128
#define HH 72
#define WW 200
#define KS 9

// ---------------------------------------------------------------------------
// One recurrence step of an H-direction sweep (conv along W, pad 4):
//   buf[b, co, r, w] += relu( bias[co] + sum_{ci,k} buf[b, ci, pr, w+k-4] * wgt[co, ci, k] )
// In-place is safe: row r holds the previous sweep's value until we write it,
// row pr was written by the previous launch (stream-ordered, L1D flushed per launch).
// Grid: (4 co-blocks of 32, 32 batches). Block: 256 threads.
// Thread tile: 2 co x 13 w (16 co-groups x 16 w-groups covers 208 >= 200).
// ---------------------------------------------------------------------------
__global__ __launch_bounds__(256) void hstep(
    float* __restrict__ buf, const float* __restrict__ wgt,
    const float* __restrict__ bias, int r, int pr)
{
    __shared__ float pS[16 * 216];       // prev-row slice, 16 ci, x = w + 4 (zero-padded)
    __shared__ float wS[16 * 9 * 32];    // weight tile [ci][k][co]

    const int b   = blockIdx.y;
    const int co0 = blockIdx.x * 32;
    const int tid = threadIdx.x;
    const int tc  = tid & 15;            // co-pair group: co = co0 + 2*tc
    const int tw  = tid >> 4;            // 0..15
    const int wb  = tw * 13;

    float acc0[13], acc1[13];
#pragma unroll
    for (int j = 0; j < 13; ++j) { acc0[j] = 0.f; acc1[j] = 0.f; }

    const size_t bbase = (size_t)b * CC * HH * WW;
    const float* prow  = buf + bbase + (size_t)pr * WW;   // + ci*H*W + w

#pragma unroll 1
    for (int cb = 0; cb < 8; ++cb) {
        const int ci0 = cb * 16;
        __syncthreads();
        // Stage prev row (ci-block) with zero pad; coalesced along w.
        for (int i = tid; i < 16 * 216; i += 256) {
            int ci = i / 216;
            int x  = i - ci * 216;
            int w  = x - 4;
            float v = 0.f;
            if (w >= 0 && w < WW) v = prow[(size_t)(ci0 + ci) * (HH * WW) + w];
            pS[i] = v;
        }
        // Stage weights: per co, 144 contiguous floats (16 ci x 9 k). Coalesced.
        for (int i = tid; i < 32 * 144; i += 256) {
            int c = i / 144;
            int f = i - c * 144;                       // f = ci*9 + k
            wS[f * 32 + c] = wgt[(size_t)(co0 + c) * (CC * KS) + ci0 * KS + f];
        }
        __syncthreads();
#pragma unroll 1
        for (int ci = 0; ci < 16; ++ci) {
            float p[21];                               // sliding window: 13 outputs + 8 taps
#pragma unroll
            for (int j = 0; j < 21; ++j) p[j] = pS[ci * 216 + wb + j];
            const float* wr = &wS[ci * 9 * 32];
#pragma unroll
            for (int k = 0; k < 9; ++k) {
                float w0 = wr[k * 32 + 2 * tc];
                float w1 = wr[k * 32 + 2 * tc + 1];
#pragma unroll
                for (int j = 0; j < 13; ++j) {
                    acc0[j] = fmaf(w0, p[j + k], acc0[j]);
                    acc1[j] = fmaf(w1, p[j + k], acc1[j]);
                }
            }
        }
    }

    const int coA = co0 + 2 * tc;
    const float bA = bias[coA];
    const float bB = bias[coA + 1];
    float* rowA = buf + bbase + (size_t)coA * (HH * WW) + (size_t)r * WW;
    float* rowB = rowA + (size_t)(HH * WW);
#pragma unroll
    for (int j = 0; j < 13; ++j) {
        int w = wb + j;
        if (w < WW) {
            float tA = acc0[j] + bA;
            float tB = acc1[j] + bB;
            rowA[w] += tA > 0.f ? tA : 0.f;
            rowB[w] += tB > 0.f ? tB : 0.f;
        }
    }
}

// ---------------------------------------------------------------------------
// One recurrence step of a W-direction sweep (conv along H, pad 4):
//   buf[b, co, h, r] += relu( bias[co] + sum_{ci,k} buf[b, ci, h+k-4, pr] * wgt[co, ci, k] )
// Thread tile: 1 co x 9 h (32 co-groups x 8 h-groups = exact 72-row cover, zero waste).
// ---------------------------------------------------------------------------
__global__ __launch_bounds__(256) void wstep(
    float* __restrict__ buf, const float* __restrict__ wgt,
    const float* __restrict__ bias, int r, int pr)
{
    __shared__ float pS[16 * 80];        // prev-column slice, x = h + 4 (zero-padded)
    __shared__ float wS[16 * 9 * 32];

    const int b   = blockIdx.y;
    const int co0 = blockIdx.x * 32;
    const int tid = threadIdx.x;
    const int tc  = tid & 31;            // co = co0 + tc
    const int th  = tid >> 5;            // 0..7
    const int hb  = th * 9;

    float acc[9];
#pragma unroll
    for (int j = 0; j < 9; ++j) acc[j] = 0.f;

    const size_t bbase = (size_t)b * CC * HH * WW;
    const float* pcol  = buf + bbase + pr;               // + ci*H*W + h*W

#pragma unroll 1
    for (int cb = 0; cb < 8; ++cb) {
        const int ci0 = cb * 16;
        __syncthreads();
        for (int i = tid; i < 16 * 80; i += 256) {
            int ci = i / 80;
            int x  = i - ci * 80;
            int h  = x - 4;
            float v = 0.f;
            if (h >= 0 && h < HH)
                v = pcol[(size_t)(ci0 + ci) * (HH * WW) + (size_t)h * WW];
            pS[i] = v;
        }
        for (int i = tid; i < 32 * 144; i += 256) {
            int c = i / 144;
            int f = i - c * 144;
            wS[f * 32 + c] = wgt[(size_t)(co0 + c) * (CC * KS) + ci0 * KS + f];
        }
        __syncthreads();
#pragma unroll 1
        for (int ci = 0; ci < 16; ++ci) {
            float p[17];                                // 9 outputs + 8 taps
#pragma unroll
            for (int j = 0; j < 17; ++j) p[j] = pS[ci * 80 + hb + j];
            const float* wr = &wS[ci * 9 * 32];
#pragma unroll
            for (int k = 0; k < 9; ++k) {
                float w0 = wr[k * 32 + tc];
#pragma unroll
                for (int j = 0; j < 9; ++j)
                    acc[j] = fmaf(w0, p[j + k], acc[j]);
            }
        }
    }

    const int co = co0 + tc;
    const float bs = bias[co];
    float* colp = buf + bbase + (size_t)co * (HH * WW) + r;
#pragma unroll
    for (int j = 0; j < 9; ++j) {
        int h = hb + j;
        float t = acc[j] + bs;
        colp[(size_t)h * WW] += t > 0.f ? t : 0.f;
    }
}

// ---------------------------------------------------------------------------
// Launcher: copy x -> out, then 4 in-place sweeps as chains of step kernels.
// Everything is default-stream, graph-capturable, allocation-free.
// ---------------------------------------------------------------------------
extern "C" void kernel_launch(void* const* d_in, const int* in_sizes, int n_in,
                              void* d_out, int out_size)
{
    const float* x  = (const float*)d_in[0];
    const float* wd = (const float*)d_in[1];
    const float* bd = (const float*)d_in[2];
    const float* wu = (const float*)d_in[3];
    const float* bu = (const float*)d_in[4];
    const float* wr = (const float*)d_in[5];
    const float* br = (const float*)d_in[6];
    const float* wl = (const float*)d_in[7];
    const float* bl = (const float*)d_in[8];
    float* out = (float*)d_out;

    const size_t bytes = (size_t)BB * CC * HH * WW * sizeof(float);
    cudaMemcpyAsync(out, x, bytes, cudaMemcpyDeviceToDevice);

    dim3 grid(4, BB);

    // Sweep D: axis H, forward
    for (int h = 1; h < HH; ++h)
        hstep<<<grid, 256>>>(out, wd, bd, h, h - 1);
    // Sweep U: axis H, reverse
    for (int h = HH - 2; h >= 0; --h)
        hstep<<<grid, 256>>>(out, wu, bu, h, h + 1);
    // Sweep R: axis W, forward
    for (int w = 1; w < WW; ++w)
        wstep<<<grid, 256>>>(out, wr, br, w, w - 1);
    // Sweep L: axis W, reverse
    for (int w = WW - 2; w >= 0; --w)
        wstep<<<grid, 256>>>(out, wl, bl, w, w + 1);
}

// round 3
// speedup vs baseline: 1.1337x; 1.1330x over previous
#include <cuda_runtime.h>
#include <cstddef>

#define BB 32
#define CC 128
#define HH 72
#define WW 200
#define KS 9
#define HW (HH * WW)

#define PSTR 240                    // padded row stride in smem (w+4 window, overrun-safe)
#define H_PS (CC * PSTR)            // 30720 floats = 122880 B
#define CSTR 80                     // padded column stride (h+4)
#define W_PS (CC * CSTR)            // 10240 floats = 40960 B
#define WCHUNK (16 * KS * 32)       // 4608 floats per (16 ci x 32 co) weight chunk

// ---------------- packed f32x2 helpers (sm_103a FFMA2) ----------------
__device__ __forceinline__ unsigned long long f2pk(float lo, float hi) {
    unsigned long long r;
    asm("mov.b64 %0, {%1, %2};" : "=l"(r) : "f"(lo), "f"(hi));
    return r;
}
__device__ __forceinline__ void f2un(float& lo, float& hi, unsigned long long v) {
    asm("mov.b64 {%0, %1}, %2;" : "=f"(lo), "=f"(hi) : "l"(v));
}
__device__ __forceinline__ unsigned long long ffma2(unsigned long long a,
                                                    unsigned long long b,
                                                    unsigned long long c) {
    unsigned long long d;
    asm("fma.rn.f32x2 %0, %1, %2, %3;" : "=l"(d) : "l"(a), "l"(b), "l"(c));
    return d;
}

// ---------------------------------------------------------------------------
// H-sweep step: buf[b,co,r,w] += relu(bias[co] + sum_{ci,k} buf[b,ci,pr,w+k-4]*wgt[co,ci,k])
// grid (4 co-blocks, 32 b), 512 threads. lane=co (tc 0..31), warp=w-group (tw 0..15, 14 w each).
// smem: full prev row (128ci x 240) + double-buffered weight chunks.
// ---------------------------------------------------------------------------
__global__ __launch_bounds__(512) void hstep(
    float* __restrict__ buf, const float* __restrict__ wgt,
    const float* __restrict__ bias, int r, int pr)
{
    extern __shared__ float sm[];
    float* pS = sm;                    // [128][PSTR]
    float* wS = sm + H_PS;             // [2][WCHUNK], layout [f*32 + co]

    const int b   = blockIdx.y;
    const int co0 = blockIdx.x * 32;
    const int tid = threadIdx.x;
    const int tc  = tid & 31;
    const int tw  = tid >> 5;          // 0..15
    const int wb  = tw * 14;

    const size_t bbase = (size_t)b * CC * HW;
    const float* prow  = buf + bbase + (size_t)pr * WW;

    // Stage full prev row (zero-padded halo + tail).
    for (int i = tid; i < H_PS; i += 512) {
        int ci = i / PSTR;
        int w  = i - ci * PSTR - 4;
        pS[i] = (w >= 0 && w < WW) ? prow[(size_t)ci * HW + w] : 0.f;
    }
    // Stage weight chunk 0: per co, 144 contiguous floats (16 ci x 9 k).
    {
        const float* wsrc = wgt + (size_t)co0 * (CC * KS);
        for (int i = tid; i < WCHUNK; i += 512) {
            int c = i / 144;
            int f = i - c * 144;
            wS[f * 32 + c] = wsrc[c * (CC * KS) + f];
        }
    }
    __syncthreads();

    unsigned long long acc[7];
#pragma unroll
    for (int j = 0; j < 7; ++j) acc[j] = 0ull;

#pragma unroll 1
    for (int cb = 0; cb < 8; ++cb) {
        float* wcur = wS + (cb & 1) * WCHUNK;

        // Prefetch next weight chunk into registers (overlaps compute).
        float wr9[9];
        int pc[9], pf[9];
        if (cb < 7) {
            const float* wsrc = wgt + (size_t)co0 * (CC * KS) + (cb + 1) * 16 * KS;
#pragma unroll
            for (int j = 0; j < 9; ++j) {
                int i = tid + j * 512;
                pc[j] = i / 144;
                pf[j] = i - pc[j] * 144;
                wr9[j] = wsrc[pc[j] * (CC * KS) + pf[j]];
            }
        }

#pragma unroll 2
        for (int ci16 = 0; ci16 < 16; ++ci16) {
            const float* prp = &pS[(cb * 16 + ci16) * PSTR + wb];
            float p[22];
#pragma unroll
            for (int i = 0; i < 22; ++i) p[i] = prp[i];
            unsigned long long A[11], Bv[10];
#pragma unroll
            for (int i = 0; i < 11; ++i) A[i] = f2pk(p[2 * i], p[2 * i + 1]);
#pragma unroll
            for (int i = 0; i < 10; ++i) Bv[i] = f2pk(p[2 * i + 1], p[2 * i + 2]);

            const float* wr = &wcur[(ci16 * KS) * 32 + tc];
#pragma unroll
            for (int k = 0; k < 9; ++k) {
                float wv = wr[k * 32];
                unsigned long long wp = f2pk(wv, wv);
#pragma unroll
                for (int j = 0; j < 7; ++j) {
                    unsigned long long src = (k & 1) ? Bv[(k >> 1) + j] : A[(k >> 1) + j];
                    acc[j] = ffma2(wp, src, acc[j]);
                }
            }
        }

        if (cb < 7) {
            float* wnxt = wS + ((cb + 1) & 1) * WCHUNK;
#pragma unroll
            for (int j = 0; j < 9; ++j) wnxt[pf[j] * 32 + pc[j]] = wr9[j];
        }
        __syncthreads();
    }

    const int co = co0 + tc;
    const float bv = bias[co];
    float* row = buf + bbase + (size_t)co * HW + (size_t)r * WW;
#pragma unroll
    for (int j = 0; j < 7; ++j) {
        float lo, hi;
        f2un(lo, hi, acc[j]);
        int w = wb + 2 * j;
        if (w < WW) {
            float t = lo + bv;
            row[w] += t > 0.f ? t : 0.f;
        }
        if (w + 1 < WW) {
            float t = hi + bv;
            row[w + 1] += t > 0.f ? t : 0.f;
        }
    }
}

// ---------------------------------------------------------------------------
// W-sweep step: buf[b,co,h,r] += relu(bias[co] + sum_{ci,k} buf[b,ci,h+k-4,pr]*wgt[co,ci,k])
// grid (4, 32), 384 threads. lane=co, warp=h-group (th 0..11, 6 h each: exact 72 cover).
// ---------------------------------------------------------------------------
__global__ __launch_bounds__(384) void wstep(
    float* __restrict__ buf, const float* __restrict__ wgt,
    const float* __restrict__ bias, int r, int pr)
{
    extern __shared__ float sm[];
    float* pS = sm;                    // [128][CSTR]
    float* wS = sm + W_PS;             // [2][WCHUNK]

    const int b   = blockIdx.y;
    const int co0 = blockIdx.x * 32;
    const int tid = threadIdx.x;
    const int tc  = tid & 31;
    const int th  = tid >> 5;          // 0..11
    const int hb  = th * 6;

    const size_t bbase = (size_t)b * CC * HW;
    const float* pcol  = buf + bbase + pr;

    for (int i = tid; i < W_PS; i += 384) {
        int ci = i / CSTR;
        int h  = i - ci * CSTR - 4;
        pS[i] = (h >= 0 && h < HH) ? pcol[(size_t)ci * HW + (size_t)h * WW] : 0.f;
    }
    {
        const float* wsrc = wgt + (size_t)co0 * (CC * KS);
        for (int i = tid; i < WCHUNK; i += 384) {
            int c = i / 144;
            int f = i - c * 144;
            wS[f * 32 + c] = wsrc[c * (CC * KS) + f];
        }
    }
    __syncthreads();

    unsigned long long acc[3];
#pragma unroll
    for (int j = 0; j < 3; ++j) acc[j] = 0ull;

#pragma unroll 1
    for (int cb = 0; cb < 8; ++cb) {
        float* wcur = wS + (cb & 1) * WCHUNK;

        float wr12[12];
        int pc[12], pf[12];
        if (cb < 7) {
            const float* wsrc = wgt + (size_t)co0 * (CC * KS) + (cb + 1) * 16 * KS;
#pragma unroll
            for (int j = 0; j < 12; ++j) {
                int i = tid + j * 384;
                pc[j] = i / 144;
                pf[j] = i - pc[j] * 144;
                wr12[j] = wsrc[pc[j] * (CC * KS) + pf[j]];
            }
        }

#pragma unroll 2
        for (int ci16 = 0; ci16 < 16; ++ci16) {
            const float* prp = &pS[(cb * 16 + ci16) * CSTR + hb];
            float p[14];
#pragma unroll
            for (int i = 0; i < 14; ++i) p[i] = prp[i];
            unsigned long long A[7], Bv[6];
#pragma unroll
            for (int i = 0; i < 7; ++i) A[i] = f2pk(p[2 * i], p[2 * i + 1]);
#pragma unroll
            for (int i = 0; i < 6; ++i) Bv[i] = f2pk(p[2 * i + 1], p[2 * i + 2]);

            const float* wr = &wcur[(ci16 * KS) * 32 + tc];
#pragma unroll
            for (int k = 0; k < 9; ++k) {
                float wv = wr[k * 32];
                unsigned long long wp = f2pk(wv, wv);
#pragma unroll
                for (int j = 0; j < 3; ++j) {
                    unsigned long long src = (k & 1) ? Bv[(k >> 1) + j] : A[(k >> 1) + j];
                    acc[j] = ffma2(wp, src, acc[j]);
                }
            }
        }

        if (cb < 7) {
            float* wnxt = wS + ((cb + 1) & 1) * WCHUNK;
#pragma unroll
            for (int j = 0; j < 12; ++j) wnxt[pf[j] * 32 + pc[j]] = wr12[j];
        }
        __syncthreads();
    }

    const int co = co0 + tc;
    const float bv = bias[co];
    float* col = buf + bbase + (size_t)co * HW + r;
#pragma unroll
    for (int j = 0; j < 3; ++j) {
        float lo, hi;
        f2un(lo, hi, acc[j]);
        int h = hb + 2 * j;
        float t0 = lo + bv;
        col[(size_t)h * WW] += t0 > 0.f ? t0 : 0.f;
        float t1 = hi + bv;
        col[(size_t)(h + 1) * WW] += t1 > 0.f ? t1 : 0.f;
    }
}

// ---------------------------------------------------------------------------
extern "C" void kernel_launch(void* const* d_in, const int* in_sizes, int n_in,
                              void* d_out, int out_size)
{
    const float* x  = (const float*)d_in[0];
    const float* wd = (const float*)d_in[1];
    const float* bd = (const float*)d_in[2];
    const float* wu = (const float*)d_in[3];
    const float* bu = (const float*)d_in[4];
    const float* wr = (const float*)d_in[5];
    const float* br = (const float*)d_in[6];
    const float* wl = (const float*)d_in[7];
    const float* bl = (const float*)d_in[8];
    float* out = (float*)d_out;

    const int hsm = (H_PS + 2 * WCHUNK) * sizeof(float);   // 159,744 B
    const int wsm = (W_PS + 2 * WCHUNK) * sizeof(float);   //  77,824 B
    cudaFuncSetAttribute(hstep, cudaFuncAttributeMaxDynamicSharedMemorySize, hsm);
    cudaFuncSetAttribute(wstep, cudaFuncAttributeMaxDynamicSharedMemorySize, wsm);

    const size_t bytes = (size_t)BB * CC * HW * sizeof(float);
    cudaMemcpyAsync(out, x, bytes, cudaMemcpyDeviceToDevice);

    dim3 grid(4, BB);

    for (int h = 1; h < HH; ++h)
        hstep<<<grid, 512, hsm>>>(out, wd, bd, h, h - 1);
    for (int h = HH - 2; h >= 0; --h)
        hstep<<<grid, 512, hsm>>>(out, wu, bu, h, h + 1);
    for (int w = 1; w < WW; ++w)
        wstep<<<grid, 384, wsm>>>(out, wr, br, w, w - 1);
    for (int w = WW - 2; w >= 0; --w)
        wstep<<<grid, 384, wsm>>>(out, wl, bl, w, w + 1);
}

// round 4
// speedup vs baseline: 1.4391x; 1.2694x over previous
#include <cuda_runtime.h>
#include <cstddef>

#define BB 32
#define CC 128
#define HH 72
#define WW 200
#define KS 9
#define HW (HH * WW)

#define PSTR 240                    // padded row stride (w+4 halo), 960B = 16B-aligned rows
#define H_PS (CC * PSTR)            // 30720 floats
#define CSTR 80                     // padded column stride (h+4), 320B rows
#define W_PS (CC * CSTR)            // 10240 floats
#define WSTR 12                     // padded k-stride per (ci,co): 3 x float4
#define WCH  (16 * 32 * WSTR)       // 6144 floats per buffered weight chunk

#define H_NT 800                    // 25 warps x 8 w = 200 exact
#define W_NT 576                    // 18 warps x 4 h = 72 exact

// ---------------- packed f32x2 helpers (sm_103a FFMA2) ----------------
__device__ __forceinline__ unsigned long long f2pk(float lo, float hi) {
    unsigned long long r;
    asm("mov.b64 %0, {%1, %2};" : "=l"(r) : "f"(lo), "f"(hi));
    return r;
}
__device__ __forceinline__ void f2un(float& lo, float& hi, unsigned long long v) {
    asm("mov.b64 {%0, %1}, %2;" : "=f"(lo), "=f"(hi) : "l"(v));
}
__device__ __forceinline__ unsigned long long ffma2(unsigned long long a,
                                                    unsigned long long b,
                                                    unsigned long long c) {
    unsigned long long d;
    asm("fma.rn.f32x2 %0, %1, %2, %3;" : "=l"(d) : "l"(a), "l"(b), "l"(c));
    return d;
}

// ---------------------------------------------------------------------------
// H-sweep step: buf[b,co,r,w] += relu(bias[co] + sum_{ci,k} buf[b,ci,pr,w+k-4]*wgt[co,ci,k])
// grid (4 co-blocks, 32 b), 800 threads. lane=co, warp=w-group of 8 (exact cover).
// All smem reads are LDS.128; window reads are warp-broadcast.
// ---------------------------------------------------------------------------
__global__ __launch_bounds__(H_NT) void hstep(
    float* __restrict__ buf, const float* __restrict__ wgt,
    const float* __restrict__ bias, int r, int pr)
{
    extern __shared__ float sm[];
    float* pS = sm;                    // [128][PSTR]
    float* wS = sm + H_PS;             // [2][16 ci][32 co][WSTR]

    const int b   = blockIdx.y;
    const int co0 = blockIdx.x * 32;
    const int tid = threadIdx.x;
    const int tc  = tid & 31;          // co lane
    const int tw  = tid >> 5;          // 0..24
    const int wb  = tw * 8;            // 16B-aligned window base

    const size_t bbase = (size_t)b * CC * HW;
    const float* prow  = buf + bbase + (size_t)pr * WW;

    // Stage full prev row (zero-padded halo + tail), coalesced.
    for (int i = tid; i < H_PS; i += H_NT) {
        int ci = i / PSTR;
        int w  = i - ci * PSTR - 4;
        pS[i] = (w >= 0 && w < WW) ? prow[(size_t)ci * HW + w] : 0.f;
    }
    // Stage weight chunk 0 into padded layout [(ci*32+co)*12 + k].
    {
        const float* wsrc = wgt + (size_t)co0 * (CC * KS);
        for (int i = tid; i < 16 * 32 * KS; i += H_NT) {
            int c = i / 144;
            int f = i - c * 144;       // f = ci*9 + k
            int ci = f / 9, k = f - ci * 9;
            wS[(ci * 32 + c) * WSTR + k] = wsrc[c * (CC * KS) + f];
        }
    }
    __syncthreads();

    unsigned long long acc[4];
#pragma unroll
    for (int j = 0; j < 4; ++j) acc[j] = 0ull;

#pragma unroll 1
    for (int cb = 0; cb < 8; ++cb) {
        const float* wcur = wS + (cb & 1) * WCH;

        // Prefetch next weight chunk into registers (overlaps compute).
        float pw[6];
        int   pidx[6];
        if (cb < 7) {
            const float* wsrc = wgt + (size_t)co0 * (CC * KS) + (cb + 1) * 16 * KS;
#pragma unroll
            for (int j = 0; j < 6; ++j) {
                int i = tid + j * H_NT;
                if (i < 16 * 32 * KS) {
                    int c = i / 144;
                    int f = i - c * 144;
                    int ci = f / 9, k = f - ci * 9;
                    pw[j]   = wsrc[c * (CC * KS) + f];
                    pidx[j] = (ci * 32 + c) * WSTR + k;
                } else pidx[j] = -1;
            }
        }

#pragma unroll 1
        for (int ci16 = 0; ci16 < 16; ++ci16) {
            // Window: 16 floats via 4 broadcast LDS.128.
            const float4* pq = (const float4*)&pS[(cb * 16 + ci16) * PSTR + wb];
            float4 q0 = pq[0], q1 = pq[1], q2 = pq[2], q3 = pq[3];
            float p[16] = {q0.x,q0.y,q0.z,q0.w, q1.x,q1.y,q1.z,q1.w,
                           q2.x,q2.y,q2.z,q2.w, q3.x,q3.y,q3.z,q3.w};
            unsigned long long A[8], Bv[7];
#pragma unroll
            for (int i = 0; i < 8; ++i) A[i] = f2pk(p[2*i], p[2*i+1]);
#pragma unroll
            for (int i = 0; i < 7; ++i) Bv[i] = f2pk(p[2*i+1], p[2*i+2]);

            // Weights: 9 taps via 3 LDS.128 (conflict-free stride 12).
            const float4* wq = (const float4*)&wcur[(ci16 * 32 + tc) * WSTR];
            float4 w0 = wq[0], w1 = wq[1], w2 = wq[2];
            float wk[9] = {w0.x,w0.y,w0.z,w0.w, w1.x,w1.y,w1.z,w1.w, w2.x};

#pragma unroll
            for (int k = 0; k < 9; ++k) {
                unsigned long long wp = f2pk(wk[k], wk[k]);
#pragma unroll
                for (int j = 0; j < 4; ++j) {
                    unsigned long long src = (k & 1) ? Bv[(k >> 1) + j] : A[(k >> 1) + j];
                    acc[j] = ffma2(wp, src, acc[j]);
                }
            }
        }

        if (cb < 7) {
            float* wnxt = wS + ((cb + 1) & 1) * WCH;
#pragma unroll
            for (int j = 0; j < 6; ++j)
                if (pidx[j] >= 0) wnxt[pidx[j]] = pw[j];
        }
        __syncthreads();
    }

    const int co = co0 + tc;
    const float bv = bias[co];
    float* row = buf + bbase + (size_t)co * HW + (size_t)r * WW + wb;
#pragma unroll
    for (int j = 0; j < 4; ++j) {
        float lo, hi;
        f2un(lo, hi, acc[j]);
        float t0 = lo + bv;
        float t1 = hi + bv;
        row[2*j]     += t0 > 0.f ? t0 : 0.f;
        row[2*j + 1] += t1 > 0.f ? t1 : 0.f;
    }
}

// ---------------------------------------------------------------------------
// W-sweep step: buf[b,co,h,r] += relu(bias[co] + sum_{ci,k} buf[b,ci,h+k-4,pr]*wgt[co,ci,k])
// grid (4, 32), 576 threads. lane=co, warp=h-group of 4 (exact 72 cover).
// ---------------------------------------------------------------------------
__global__ __launch_bounds__(W_NT) void wstep(
    float* __restrict__ buf, const float* __restrict__ wgt,
    const float* __restrict__ bias, int r, int pr)
{
    extern __shared__ float sm[];
    float* pS = sm;                    // [128][CSTR]
    float* wS = sm + W_PS;             // [2][16][32][WSTR]

    const int b   = blockIdx.y;
    const int co0 = blockIdx.x * 32;
    const int tid = threadIdx.x;
    const int tc  = tid & 31;
    const int th  = tid >> 5;          // 0..17
    const int hb  = th * 4;            // 16B-aligned

    const size_t bbase = (size_t)b * CC * HW;
    const float* pcol  = buf + bbase + pr;

    for (int i = tid; i < W_PS; i += W_NT) {
        int ci = i / CSTR;
        int h  = i - ci * CSTR - 4;
        pS[i] = (h >= 0 && h < HH) ? pcol[(size_t)ci * HW + (size_t)h * WW] : 0.f;
    }
    {
        const float* wsrc = wgt + (size_t)co0 * (CC * KS);
        for (int i = tid; i < 16 * 32 * KS; i += W_NT) {
            int c = i / 144;
            int f = i - c * 144;
            int ci = f / 9, k = f - ci * 9;
            wS[(ci * 32 + c) * WSTR + k] = wsrc[c * (CC * KS) + f];
        }
    }
    __syncthreads();

    unsigned long long acc[2];
    acc[0] = 0ull; acc[1] = 0ull;

#pragma unroll 1
    for (int cb = 0; cb < 8; ++cb) {
        const float* wcur = wS + (cb & 1) * WCH;

        float pw[8];
        int   pidx[8];
        if (cb < 7) {
            const float* wsrc = wgt + (size_t)co0 * (CC * KS) + (cb + 1) * 16 * KS;
#pragma unroll
            for (int j = 0; j < 8; ++j) {
                int i = tid + j * W_NT;
                if (i < 16 * 32 * KS) {
                    int c = i / 144;
                    int f = i - c * 144;
                    int ci = f / 9, k = f - ci * 9;
                    pw[j]   = wsrc[c * (CC * KS) + f];
                    pidx[j] = (ci * 32 + c) * WSTR + k;
                } else pidx[j] = -1;
            }
        }

#pragma unroll 2
        for (int ci16 = 0; ci16 < 16; ++ci16) {
            const float4* pq = (const float4*)&pS[(cb * 16 + ci16) * CSTR + hb];
            float4 q0 = pq[0], q1 = pq[1], q2 = pq[2];
            float p[12] = {q0.x,q0.y,q0.z,q0.w, q1.x,q1.y,q1.z,q1.w,
                           q2.x,q2.y,q2.z,q2.w};
            unsigned long long A[6], Bv[5];
#pragma unroll
            for (int i = 0; i < 6; ++i) A[i] = f2pk(p[2*i], p[2*i+1]);
#pragma unroll
            for (int i = 0; i < 5; ++i) Bv[i] = f2pk(p[2*i+1], p[2*i+2]);

            const float4* wq = (const float4*)&wcur[(ci16 * 32 + tc) * WSTR];
            float4 w0 = wq[0], w1 = wq[1], w2 = wq[2];
            float wk[9] = {w0.x,w0.y,w0.z,w0.w, w1.x,w1.y,w1.z,w1.w, w2.x};

#pragma unroll
            for (int k = 0; k < 9; ++k) {
                unsigned long long wp = f2pk(wk[k], wk[k]);
#pragma unroll
                for (int j = 0; j < 2; ++j) {
                    unsigned long long src = (k & 1) ? Bv[(k >> 1) + j] : A[(k >> 1) + j];
                    acc[j] = ffma2(wp, src, acc[j]);
                }
            }
        }

        if (cb < 7) {
            float* wnxt = wS + ((cb + 1) & 1) * WCH;
#pragma unroll
            for (int j = 0; j < 8; ++j)
                if (pidx[j] >= 0) wnxt[pidx[j]] = pw[j];
        }
        __syncthreads();
    }

    const int co = co0 + tc;
    const float bv = bias[co];
    float* col = buf + bbase + (size_t)co * HW + r;
#pragma unroll
    for (int j = 0; j < 2; ++j) {
        float lo, hi;
        f2un(lo, hi, acc[j]);
        int h = hb + 2 * j;
        float t0 = lo + bv;
        float t1 = hi + bv;
        col[(size_t)h * WW]       += t0 > 0.f ? t0 : 0.f;
        col[(size_t)(h + 1) * WW] += t1 > 0.f ? t1 : 0.f;
    }
}

// ---------------------------------------------------------------------------
extern "C" void kernel_launch(void* const* d_in, const int* in_sizes, int n_in,
                              void* d_out, int out_size)
{
    const float* x  = (const float*)d_in[0];
    const float* wd = (const float*)d_in[1];
    const float* bd = (const float*)d_in[2];
    const float* wu = (const float*)d_in[3];
    const float* bu = (const float*)d_in[4];
    const float* wr = (const float*)d_in[5];
    const float* br = (const float*)d_in[6];
    const float* wl = (const float*)d_in[7];
    const float* bl = (const float*)d_in[8];
    float* out = (float*)d_out;

    const int hsm = (H_PS + 2 * WCH) * sizeof(float);   // 172,032 B
    const int wsm = (W_PS + 2 * WCH) * sizeof(float);   //  90,112 B
    cudaFuncSetAttribute(hstep, cudaFuncAttributeMaxDynamicSharedMemorySize, hsm);
    cudaFuncSetAttribute(wstep, cudaFuncAttributeMaxDynamicSharedMemorySize, wsm);

    const size_t bytes = (size_t)BB * CC * HW * sizeof(float);
    cudaMemcpyAsync(out, x, bytes, cudaMemcpyDeviceToDevice);

    dim3 grid(4, BB);

    for (int h = 1; h < HH; ++h)
        hstep<<<grid, H_NT, hsm>>>(out, wd, bd, h, h - 1);
    for (int h = HH - 2; h >= 0; --h)
        hstep<<<grid, H_NT, hsm>>>(out, wu, bu, h, h + 1);
    for (int w = 1; w < WW; ++w)
        wstep<<<grid, W_NT, wsm>>>(out, wr, br, w, w - 1);
    for (int w = WW - 2; w >= 0; --w)
        wstep<<<grid, W_NT, wsm>>>(out, wl, bl, w, w + 1);
}

// round 5
// speedup vs baseline: 1.4413x; 1.0015x over previous
#include <cuda_runtime.h>
#include <cstddef>

#define BB 32
#define CC 128
#define HH 72
#define WW 200
#define KS 9
#define HW (HH * WW)

#define PSTR 240                    // padded row stride (w+4 halo), 960B = 16B-aligned rows
#define H_PS (CC * PSTR)            // 30720 floats
#define CSTR 80                     // padded column stride (h+4), 320B rows
#define W_PS (CC * CSTR)            // 10240 floats
#define WSTR 12                     // padded k-stride per (ci,co): 3 x float4
#define WCH  (16 * 32 * WSTR)       // 6144 floats per buffered weight chunk

#define H_NT 800                    // 25 warps x 8 w = 200 exact
#define W_NT 576                    // 18 warps x 4 h = 72 exact

// ---------------- packed f32x2 helpers (sm_103a FFMA2) ----------------
__device__ __forceinline__ unsigned long long f2pk(float lo, float hi) {
    unsigned long long r;
    asm("mov.b64 %0, {%1, %2};" : "=l"(r) : "f"(lo), "f"(hi));
    return r;
}
__device__ __forceinline__ void f2un(float& lo, float& hi, unsigned long long v) {
    asm("mov.b64 {%0, %1}, %2;" : "=f"(lo), "=f"(hi) : "l"(v));
}
__device__ __forceinline__ unsigned long long ffma2(unsigned long long a,
                                                    unsigned long long b,
                                                    unsigned long long c) {
    unsigned long long d;
    asm("fma.rn.f32x2 %0, %1, %2, %3;" : "=l"(d) : "l"(a), "l"(b), "l"(c));
    return d;
}

// ---------------------------------------------------------------------------
// H-sweep step: buf[b,co,r,w] += relu(bias[co] + sum_{ci,k} buf[b,ci,pr,w+k-4]*wgt[co,ci,k])
// grid (4 co-blocks, 32 b), 800 threads. lane=co, warp=w-group of 8 (exact cover).
// All smem reads are LDS.128; window reads are warp-broadcast.
// ---------------------------------------------------------------------------
__global__ __launch_bounds__(H_NT) void hstep(
    float* __restrict__ buf, const float* __restrict__ wgt,
    const float* __restrict__ bias, int r, int pr)
{
    extern __shared__ float sm[];
    float* pS = sm;                    // [128][PSTR]
    float* wS = sm + H_PS;             // [2][16 ci][32 co][WSTR]

    const int b   = blockIdx.y;
    const int co0 = blockIdx.x * 32;
    const int tid = threadIdx.x;
    const int tc  = tid & 31;          // co lane
    const int tw  = tid >> 5;          // 0..24
    const int wb  = tw * 8;            // 16B-aligned window base

    const size_t bbase = (size_t)b * CC * HW;
    const float* prow  = buf + bbase + (size_t)pr * WW;

    // Stage full prev row (zero-padded halo + tail), coalesced.
    for (int i = tid; i < H_PS; i += H_NT) {
        int ci = i / PSTR;
        int w  = i - ci * PSTR - 4;
        pS[i] = (w >= 0 && w < WW) ? prow[(size_t)ci * HW + w] : 0.f;
    }
    // Stage weight chunk 0 into padded layout [(ci*32+co)*12 + k].
    {
        const float* wsrc = wgt + (size_t)co0 * (CC * KS);
        for (int i = tid; i < 16 * 32 * KS; i += H_NT) {
            int c = i / 144;
            int f = i - c * 144;       // f = ci*9 + k
            int ci = f / 9, k = f - ci * 9;
            wS[(ci * 32 + c) * WSTR + k] = wsrc[c * (CC * KS) + f];
        }
    }
    __syncthreads();

    unsigned long long acc[4];
#pragma unroll
    for (int j = 0; j < 4; ++j) acc[j] = 0ull;

#pragma unroll 1
    for (int cb = 0; cb < 8; ++cb) {
        const float* wcur = wS + (cb & 1) * WCH;

        // Prefetch next weight chunk into registers (overlaps compute).
        float pw[6];
        int   pidx[6];
        if (cb < 7) {
            const float* wsrc = wgt + (size_t)co0 * (CC * KS) + (cb + 1) * 16 * KS;
#pragma unroll
            for (int j = 0; j < 6; ++j) {
                int i = tid + j * H_NT;
                if (i < 16 * 32 * KS) {
                    int c = i / 144;
                    int f = i - c * 144;
                    int ci = f / 9, k = f - ci * 9;
                    pw[j]   = wsrc[c * (CC * KS) + f];
                    pidx[j] = (ci * 32 + c) * WSTR + k;
                } else pidx[j] = -1;
            }
        }

#pragma unroll 1
        for (int ci16 = 0; ci16 < 16; ++ci16) {
            // Window: 16 floats via 4 broadcast LDS.128.
            const float4* pq = (const float4*)&pS[(cb * 16 + ci16) * PSTR + wb];
            float4 q0 = pq[0], q1 = pq[1], q2 = pq[2], q3 = pq[3];
            float p[16] = {q0.x,q0.y,q0.z,q0.w, q1.x,q1.y,q1.z,q1.w,
                           q2.x,q2.y,q2.z,q2.w, q3.x,q3.y,q3.z,q3.w};
            unsigned long long A[8], Bv[7];
#pragma unroll
            for (int i = 0; i < 8; ++i) A[i] = f2pk(p[2*i], p[2*i+1]);
#pragma unroll
            for (int i = 0; i < 7; ++i) Bv[i] = f2pk(p[2*i+1], p[2*i+2]);

            // Weights: 9 taps via 3 LDS.128 (conflict-free stride 12).
            const float4* wq = (const float4*)&wcur[(ci16 * 32 + tc) * WSTR];
            float4 w0 = wq[0], w1 = wq[1], w2 = wq[2];
            float wk[9] = {w0.x,w0.y,w0.z,w0.w, w1.x,w1.y,w1.z,w1.w, w2.x};

#pragma unroll
            for (int k = 0; k < 9; ++k) {
                unsigned long long wp = f2pk(wk[k], wk[k]);
#pragma unroll
                for (int j = 0; j < 4; ++j) {
                    unsigned long long src = (k & 1) ? Bv[(k >> 1) + j] : A[(k >> 1) + j];
                    acc[j] = ffma2(wp, src, acc[j]);
                }
            }
        }

        if (cb < 7) {
            float* wnxt = wS + ((cb + 1) & 1) * WCH;
#pragma unroll
            for (int j = 0; j < 6; ++j)
                if (pidx[j] >= 0) wnxt[pidx[j]] = pw[j];
        }
        __syncthreads();
    }

    const int co = co0 + tc;
    const float bv = bias[co];
    float* row = buf + bbase + (size_t)co * HW + (size_t)r * WW + wb;
#pragma unroll
    for (int j = 0; j < 4; ++j) {
        float lo, hi;
        f2un(lo, hi, acc[j]);
        float t0 = lo + bv;
        float t1 = hi + bv;
        row[2*j]     += t0 > 0.f ? t0 : 0.f;
        row[2*j + 1] += t1 > 0.f ? t1 : 0.f;
    }
}

// ---------------------------------------------------------------------------
// W-sweep step: buf[b,co,h,r] += relu(bias[co] + sum_{ci,k} buf[b,ci,h+k-4,pr]*wgt[co,ci,k])
// grid (4, 32), 576 threads. lane=co, warp=h-group of 4 (exact 72 cover).
// ---------------------------------------------------------------------------
__global__ __launch_bounds__(W_NT) void wstep(
    float* __restrict__ buf, const float* __restrict__ wgt,
    const float* __restrict__ bias, int r, int pr)
{
    extern __shared__ float sm[];
    float* pS = sm;                    // [128][CSTR]
    float* wS = sm + W_PS;             // [2][16][32][WSTR]

    const int b   = blockIdx.y;
    const int co0 = blockIdx.x * 32;
    const int tid = threadIdx.x;
    const int tc  = tid & 31;
    const int th  = tid >> 5;          // 0..17
    const int hb  = th * 4;            // 16B-aligned

    const size_t bbase = (size_t)b * CC * HW;
    const float* pcol  = buf + bbase + pr;

    for (int i = tid; i < W_PS; i += W_NT) {
        int ci = i / CSTR;
        int h  = i - ci * CSTR - 4;
        pS[i] = (h >= 0 && h < HH) ? pcol[(size_t)ci * HW + (size_t)h * WW] : 0.f;
    }
    {
        const float* wsrc = wgt + (size_t)co0 * (CC * KS);
        for (int i = tid; i < 16 * 32 * KS; i += W_NT) {
            int c = i / 144;
            int f = i - c * 144;
            int ci = f / 9, k = f - ci * 9;
            wS[(ci * 32 + c) * WSTR + k] = wsrc[c * (CC * KS) + f];
        }
    }
    __syncthreads();

    unsigned long long acc[2];
    acc[0] = 0ull; acc[1] = 0ull;

#pragma unroll 1
    for (int cb = 0; cb < 8; ++cb) {
        const float* wcur = wS + (cb & 1) * WCH;

        float pw[8];
        int   pidx[8];
        if (cb < 7) {
            const float* wsrc = wgt + (size_t)co0 * (CC * KS) + (cb + 1) * 16 * KS;
#pragma unroll
            for (int j = 0; j < 8; ++j) {
                int i = tid + j * W_NT;
                if (i < 16 * 32 * KS) {
                    int c = i / 144;
                    int f = i - c * 144;
                    int ci = f / 9, k = f - ci * 9;
                    pw[j]   = wsrc[c * (CC * KS) + f];
                    pidx[j] = (ci * 32 + c) * WSTR + k;
                } else pidx[j] = -1;
            }
        }

#pragma unroll 2
        for (int ci16 = 0; ci16 < 16; ++ci16) {
            const float4* pq = (const float4*)&pS[(cb * 16 + ci16) * CSTR + hb];
            float4 q0 = pq[0], q1 = pq[1], q2 = pq[2];
            float p[12] = {q0.x,q0.y,q0.z,q0.w, q1.x,q1.y,q1.z,q1.w,
                           q2.x,q2.y,q2.z,q2.w};
            unsigned long long A[6], Bv[5];
#pragma unroll
            for (int i = 0; i < 6; ++i) A[i] = f2pk(p[2*i], p[2*i+1]);
#pragma unroll
            for (int i = 0; i < 5; ++i) Bv[i] = f2pk(p[2*i+1], p[2*i+2]);

            const float4* wq = (const float4*)&wcur[(ci16 * 32 + tc) * WSTR];
            float4 w0 = wq[0], w1 = wq[1], w2 = wq[2];
            float wk[9] = {w0.x,w0.y,w0.z,w0.w, w1.x,w1.y,w1.z,w1.w, w2.x};

#pragma unroll
            for (int k = 0; k < 9; ++k) {
                unsigned long long wp = f2pk(wk[k], wk[k]);
#pragma unroll
                for (int j = 0; j < 2; ++j) {
                    unsigned long long src = (k & 1) ? Bv[(k >> 1) + j] : A[(k >> 1) + j];
                    acc[j] = ffma2(wp, src, acc[j]);
                }
            }
        }

        if (cb < 7) {
            float* wnxt = wS + ((cb + 1) & 1) * WCH;
#pragma unroll
            for (int j = 0; j < 8; ++j)
                if (pidx[j] >= 0) wnxt[pidx[j]] = pw[j];
        }
        __syncthreads();
    }

    const int co = co0 + tc;
    const float bv = bias[co];
    float* col = buf + bbase + (size_t)co * HW + r;
#pragma unroll
    for (int j = 0; j < 2; ++j) {
        float lo, hi;
        f2un(lo, hi, acc[j]);
        int h = hb + 2 * j;
        float t0 = lo + bv;
        float t1 = hi + bv;
        col[(size_t)h * WW]       += t0 > 0.f ? t0 : 0.f;
        col[(size_t)(h + 1) * WW] += t1 > 0.f ? t1 : 0.f;
    }
}

// ---------------------------------------------------------------------------
extern "C" void kernel_launch(void* const* d_in, const int* in_sizes, int n_in,
                              void* d_out, int out_size)
{
    const float* x  = (const float*)d_in[0];
    const float* wd = (const float*)d_in[1];
    const float* bd = (const float*)d_in[2];
    const float* wu = (const float*)d_in[3];
    const float* bu = (const float*)d_in[4];
    const float* wr = (const float*)d_in[5];
    const float* br = (const float*)d_in[6];
    const float* wl = (const float*)d_in[7];
    const float* bl = (const float*)d_in[8];
    float* out = (float*)d_out;

    const int hsm = (H_PS + 2 * WCH) * sizeof(float);   // 172,032 B
    const int wsm = (W_PS + 2 * WCH) * sizeof(float);   //  90,112 B
    cudaFuncSetAttribute(hstep, cudaFuncAttributeMaxDynamicSharedMemorySize, hsm);
    cudaFuncSetAttribute(wstep, cudaFuncAttributeMaxDynamicSharedMemorySize, wsm);

    const size_t bytes = (size_t)BB * CC * HW * sizeof(float);
    cudaMemcpyAsync(out, x, bytes, cudaMemcpyDeviceToDevice);

    dim3 grid(4, BB);

    for (int h = 1; h < HH; ++h)
        hstep<<<grid, H_NT, hsm>>>(out, wd, bd, h, h - 1);
    for (int h = HH - 2; h >= 0; --h)
        hstep<<<grid, H_NT, hsm>>>(out, wu, bu, h, h + 1);
    for (int w = 1; w < WW; ++w)
        wstep<<<grid, W_NT, wsm>>>(out, wr, br, w, w - 1);
    for (int w = WW - 2; w >= 0; --w)
        wstep<<<grid, W_NT, wsm>>>(out, wl, bl, w, w + 1);
}